// round 6
// baseline (speedup 1.0000x reference)
#include <cuda_runtime.h>
#include <cstdint>

// Problem dims (fixed): B=4, T=4096, D_IN=1024, H=16, D=64
#define TB 4
#define TT 4096
#define TDIN 1024
#define TH 16
#define TD 64
#define NC 64     // chunks per (b,h)
#define CT 64     // timesteps per chunk

// ---------------- scratch ----------------------------------------------------
__device__ float g_Wc[1024ull * 2048];      // tf32(RNA)-rounded W [k][n]  ( 8 MB)
__device__ float g_V [64ull * 64 * 4096];   // v[bh][d][t]                 (64 MB)
__device__ float g_S [64ull * 4096];        // s[bh][t]                    ( 1 MB)
__device__ float g_E [64 * NC];             // chunk e-sums (excl prefix)
__device__ float g_W [64ull * NC * TD];     // chunk e*v sums (excl prefix)

// ---------------- kernel 0: round W to tf32 (RNA), same layout --------------
__global__ void cvt_w_kernel(const float4* __restrict__ in)
{
    int i = blockIdx.x * blockDim.x + threadIdx.x;   // 524288 float4s
    float4 v = in[i];
    uint32_t r;
    asm("cvt.rna.tf32.f32 %0, %1;" : "=r"(r) : "f"(v.x)); v.x = __uint_as_float(r);
    asm("cvt.rna.tf32.f32 %0, %1;" : "=r"(r) : "f"(v.y)); v.y = __uint_as_float(r);
    asm("cvt.rna.tf32.f32 %0, %1;" : "=r"(r) : "f"(v.z)); v.z = __uint_as_float(r);
    asm("cvt.rna.tf32.f32 %0, %1;" : "=r"(r) : "f"(v.w)); v.w = __uint_as_float(r);
    ((float4*)g_Wc)[i] = v;
}

// ---------------- kernel 1: tf32 GEMM (BM=128,BN=128,BK=32) + epilogue ------
// 256 threads = 8 warps in 2(M) x 4(N); warp tile 64x32; 2 CTAs/SM.
// A read straight from X (HW tf32-truncates A); B from RNA-rounded g_Wc.
// smem bytes: [0,256) q; [256,2304) spart [4][128]; tiles @2560 + st*33792:
//             A 128x32 XOR-swizzled (16KB) then B 32x136-pitch (17408B).
#define STGB 33792
#define TILEB 2560

__global__ __launch_bounds__(256, 2)
void gemm_kernel(const float* __restrict__ X, const float* __restrict__ Qk)
{
    extern __shared__ float smem[];
    const uint32_t sb = (uint32_t)__cvta_generic_to_shared(smem);
    const int tid = threadIdx.x, warp = tid >> 5, lane = tid & 31;
    const int nt = blockIdx.x;               // 0..15 (head)
    const int mt = blockIdx.y;               // 0..127
    const int m0 = mt << 7, n0 = nt << 7;

    // ---- copy plans (per stage: A 4x16B, B 4x16B per thread) ----
    uint32_t aoffb[4]; const float* agp[4];
#pragma unroll
    for (int i = 0; i < 4; i++) {
        int g = tid + i * 256, row = g >> 3, c4 = g & 7;   // 128 rows x 8 f4
        aoffb[i] = row * 128 + ((c4 ^ (row & 7)) << 4);
        agp[i]   = X + (size_t)(m0 + row) * TDIN + c4 * 4;
    }
    uint32_t boffb[4]; const float* bgp[4];
#pragma unroll
    for (int i = 0; i < 4; i++) {
        int g = tid + i * 256, row = g >> 5, c4 = g & 31;  // 32 rows x 32 f4
        boffb[i] = 16384 + row * 544 + c4 * 16;
        bgp[i]   = g_Wc + (size_t)row * 2048 + n0 + c4 * 4;
    }
    auto load_stage = [&](int st, int k0) {
        uint32_t base = sb + TILEB + st * STGB;
#pragma unroll
        for (int i = 0; i < 4; i++)
            asm volatile("cp.async.cg.shared.global [%0], [%1], 16;"
                         :: "r"(base + aoffb[i]), "l"(agp[i] + k0) : "memory");
#pragma unroll
        for (int i = 0; i < 4; i++)
            asm volatile("cp.async.cg.shared.global [%0], [%1], 16;"
                         :: "r"(base + boffb[i]), "l"(bgp[i] + (size_t)k0 * 2048) : "memory");
        asm volatile("cp.async.commit_group;" ::: "memory");
    };

    load_stage(0, 0);
    load_stage(1, 32);
    if (tid < 64) smem[tid] = Qk[(nt << 6) + tid];

    // fragment addressing (R2-proven warp-tile mapping)
    const int wm = (warp >> 2) << 6;         // 0/64
    const int wc = warp & 3;                 // n quarter (32 floats)
    const int arow = wm + (lane & 15);
    const int akhi = lane >> 4, asw = arow & 7;
    const int bk = lane & 3, bn = (wc << 5) + (lane >> 2);

    float acc[4][4][4];
#pragma unroll
    for (int a = 0; a < 4; a++)
#pragma unroll
        for (int b = 0; b < 4; b++)
#pragma unroll
            for (int c = 0; c < 4; c++) acc[a][b][c] = 0.f;

    for (int kt = 0; kt < 32; kt++) {
        if (kt < 31) asm volatile("cp.async.wait_group 1;" ::: "memory");
        else         asm volatile("cp.async.wait_group 0;" ::: "memory");
        __syncthreads();
        if (kt + 2 < 32) load_stage((kt + 2) % 3, (kt + 2) << 5);

        const int cs = kt % 3;
        const uint32_t ab = sb + TILEB + cs * STGB;
        const float* Bu = (const float*)((const char*)smem + TILEB + cs * STGB + 16384)
                        + bk * 136 + bn;

#pragma unroll
        for (int ks = 0; ks < 4; ks++) {
            uint32_t afr[4][4];
#pragma unroll
            for (int mi = 0; mi < 4; mi++) {
                uint32_t addr = ab + 4u * ((arow + mi * 16) * 32 +
                                           ((((ks << 1) + akhi) ^ asw) << 2));
                asm volatile("ldmatrix.sync.aligned.m8n8.x4.shared.b16 {%0,%1,%2,%3}, [%4];"
                             : "=r"(afr[mi][0]), "=r"(afr[mi][1]),
                               "=r"(afr[mi][2]), "=r"(afr[mi][3]) : "r"(addr));
            }
            uint32_t bfr[4][2];
#pragma unroll
            for (int ni = 0; ni < 4; ni++) {
                const float* bp = Bu + (ks * 8) * 136 + ni * 8;
                bfr[ni][0] = __float_as_uint(bp[0]);
                bfr[ni][1] = __float_as_uint(bp[4 * 136]);
            }
#pragma unroll
            for (int mi = 0; mi < 4; mi++)
#pragma unroll
                for (int ni = 0; ni < 4; ni++) {
                    asm volatile("mma.sync.aligned.m16n8k8.row.col.f32.tf32.tf32.f32 "
                                 "{%0,%1,%2,%3}, {%4,%5,%6,%7}, {%8,%9}, {%0,%1,%2,%3};"
                                 : "+f"(acc[mi][ni][0]), "+f"(acc[mi][ni][1]),
                                   "+f"(acc[mi][ni][2]), "+f"(acc[mi][ni][3])
                                 : "r"(afr[mi][0]), "r"(afr[mi][1]),
                                   "r"(afr[mi][2]), "r"(afr[mi][3]),
                                   "r"(bfr[ni][0]), "r"(bfr[ni][1]));
                }
        }
    }

    // ---- epilogue: relu, V store [bh][d][t], s = sum_d q*relu(k) ----
    const int b = m0 >> 12, t0 = m0 & (TT - 1);
    const int bh = b * TH + nt;
    const int d0 = (wc << 4) + (lane & 3);
    float qv[4];
#pragma unroll
    for (int ni = 0; ni < 4; ni++) qv[ni] = smem[d0 + ni * 4];
    float* vbase = g_V + (size_t)bh * (64 * 4096);

#pragma unroll
    for (int mi = 0; mi < 4; mi++) {
#pragma unroll
        for (int hf = 0; hf < 2; hf++) {
            float sp = 0.f;
            const int row = wm + mi * 16 + (lane >> 2) + hf * 8;  // 0..127
#pragma unroll
            for (int ni = 0; ni < 4; ni++) {
                const int d = d0 + ni * 4;
                float kk = fmaxf(acc[mi][ni][hf * 2], 0.f);
                float vv = fmaxf(acc[mi][ni][hf * 2 + 1], 0.f);
                sp = fmaf(qv[ni], kk, sp);
                vbase[(size_t)d * 4096 + t0 + row] = vv;
            }
            sp += __shfl_xor_sync(0xffffffffu, sp, 1);
            sp += __shfl_xor_sync(0xffffffffu, sp, 2);
            if ((lane & 3) == 0) smem[64 + wc * 128 + row] = sp;
        }
    }
    __syncthreads();
    if (tid < 128) {
        float s = smem[64 + tid] + smem[64 + 128 + tid]
                + smem[64 + 256 + tid] + smem[64 + 384 + tid];
        g_S[(size_t)bh * TT + t0 + tid] = s;
    }
}

// ---------------- kernel 2: chunk E/W partials + in-block exclusive scan ----
// One block per bh, 256 threads. es row in smem; W via float4 V stream.
__global__ __launch_bounds__(256) void chunk_kernel()
{
    __shared__ float es[TT];          // 16KB: exp(s)
    __shared__ float ws[NC][TD];      // 16KB: chunk e*v sums
    __shared__ float eagg[NC];
    const int bh = blockIdx.x, tid = threadIdx.x;
    const int lane = tid & 31, w = tid >> 5;

    const float* sp = g_S + (size_t)bh * TT;
    for (int i = tid; i < TT; i += 256) es[i] = __expf(sp[i]);
    __syncthreads();

    // per-chunk E (warp w handles chunks w, w+8, ...)
    for (int c = w; c < NC; c += 8) {
        float e = es[c * CT + lane] + es[c * CT + 32 + lane];
#pragma unroll
        for (int o = 16; o; o >>= 1) e += __shfl_xor_sync(0xffffffffu, e, o);
        if (lane == 0) eagg[c] = e;
    }

    // per-(chunk,d) W: thread = (chgrp = tid>>6, d = tid&63)
    const int d = tid & 63;
    const float* vrow = g_V + ((size_t)bh * 64 + d) * 4096;
    for (int cg = 0; cg < 16; cg++) {
        int ch = (tid >> 6) + cg * 4;
        const float4* vp4 = (const float4*)(vrow + ch * CT);
        float wv = 0.f;
#pragma unroll
        for (int j = 0; j < 16; j++) {
            float4 v = vp4[j];
            wv = fmaf(es[ch * CT + 4 * j],     v.x, wv);
            wv = fmaf(es[ch * CT + 4 * j + 1], v.y, wv);
            wv = fmaf(es[ch * CT + 4 * j + 2], v.z, wv);
            wv = fmaf(es[ch * CT + 4 * j + 3], v.w, wv);
        }
        ws[ch][d] = wv;
    }
    __syncthreads();

    // exclusive scans -> global
    if (tid < 64) {
        float a = 0.f;
#pragma unroll
        for (int c = 0; c < NC; c++) {
            float t = ws[c][tid];
            g_W[((size_t)bh * NC + c) * TD + tid] = a;
            a += t;
        }
    } else if (tid == 64) {
        float a = 0.f;
#pragma unroll
        for (int c = 0; c < NC; c++) {
            float t = eagg[c];
            g_E[bh * NC + c] = a;
            a += t;
        }
    }
}

// ---------------- kernel 3: local scan + head-sum -> out --------------------
__global__ __launch_bounds__(1024) void final_kernel(float* __restrict__ out)
{
    __shared__ float es_s[1024], rc_s[1024], p_s[16 * 4 * 64], wtot[16];
    const int ch = blockIdx.x, b = blockIdx.y, tid = threadIdx.x;
    const int h = tid >> 6, t = tid & 63, lane = tid & 31, uh = (tid >> 5) & 1;
    const int bh = b * TH + h;

    float e = __expf(g_S[(size_t)bh * TT + ch * CT + t]);
    es_s[tid] = e;
    float p = e;
#pragma unroll
    for (int o = 1; o < 32; o <<= 1) {
        float x = __shfl_up_sync(0xffffffffu, p, o);
        if (lane >= o) p += x;
    }
    if (lane == 31 && uh == 0) wtot[h] = p;
    __syncthreads();
    float pref = p + (uh ? wtot[h] : 0.f);
    rc_s[tid] = 1.0f / (g_E[bh * NC + ch] + pref);
    __syncthreads();

    const int d = t;                                 // phase B mapping
    float a = g_W[((size_t)bh * NC + ch) * TD + d];  // exclusive prefix
    const float4* vp4 = (const float4*)(g_V + ((size_t)bh * 64 + d) * 4096 + ch * CT);
    float* outb = out + ((size_t)b * TT + ch * CT) * TD;

    for (int g4 = 0; g4 < 16; g4++) {
        float4 v = vp4[g4];
        a = fmaf(es_s[h * 64 + g4 * 4 + 0], v.x, a);
        p_s[(h * 4 + 0) * 64 + d] = a * rc_s[h * 64 + g4 * 4 + 0];
        a = fmaf(es_s[h * 64 + g4 * 4 + 1], v.y, a);
        p_s[(h * 4 + 1) * 64 + d] = a * rc_s[h * 64 + g4 * 4 + 1];
        a = fmaf(es_s[h * 64 + g4 * 4 + 2], v.z, a);
        p_s[(h * 4 + 2) * 64 + d] = a * rc_s[h * 64 + g4 * 4 + 2];
        a = fmaf(es_s[h * 64 + g4 * 4 + 3], v.w, a);
        p_s[(h * 4 + 3) * 64 + d] = a * rc_s[h * 64 + g4 * 4 + 3];
        __syncthreads();
        if (tid < 256) {
            int tt = tid >> 6, dd = tid & 63;
            float s = 0.f;
#pragma unroll
            for (int hh = 0; hh < 16; hh++) s += p_s[(hh * 4 + tt) * 64 + dd];
            outb[(size_t)(g4 * 4 + tt) * TD + dd] = s;
        }
        __syncthreads();
    }
}

// ---------------- launch ----------------------------------------------------
extern "C" void kernel_launch(void* const* d_in, const int* in_sizes, int n_in,
                              void* d_out, int out_size)
{
    const float* x = (const float*)d_in[0];   // inputs    [4,4096,1024]
    const float* w = (const float*)d_in[1];   // kv_kernel [1024,16,64,2]
    const float* q = (const float*)d_in[2];   // q_kernel  [16,64]
    float* out = (float*)d_out;               // [4,4096,64] f32

    cvt_w_kernel<<<2048, 256>>>((const float4*)w);

    cudaFuncSetAttribute(gemm_kernel,
                         cudaFuncAttributeMaxDynamicSharedMemorySize, 103936);
    gemm_kernel<<<dim3(16, 128), 256, 103936>>>(x, q);

    chunk_kernel<<<64, 256>>>();
    final_kernel<<<dim3(NC, TB), 1024>>>(out);
}

// round 8
// speedup vs baseline: 1.5510x; 1.5510x over previous
#include <cuda_runtime.h>
#include <cuda_fp16.h>
#include <cstdint>

// Problem dims (fixed): B=4, T=4096, D_IN=1024, H=16, D=64
#define TB 4
#define TT 4096
#define TDIN 1024
#define TH 16
#define TD 64
#define NC 64     // chunks per (b,h)
#define CT 64     // timesteps per chunk

// ---------------- scratch ----------------------------------------------------
__device__ __half g_Xh[16384ull * 1024];    // fp16 X [m][k]              (32 MB)
__device__ __half g_Wh[1024ull * 2048];     // fp16 W [k][n]              ( 4 MB)
__device__ float  g_V [64ull * 64 * 4096];  // v[bh][d][t]                (64 MB)
__device__ float  g_S [64ull * 4096];       // s[bh][t]                   ( 1 MB)
__device__ float  g_E [64 * NC];            // chunk e-sums (excl prefix)
__device__ float  g_W [64ull * NC * TD];    // chunk e*v sums (excl prefix)

// ---------------- kernel 0: convert inputs to fp16 --------------------------
__global__ void cvt_x_kernel(const float4* __restrict__ in)
{
    int i = blockIdx.x * blockDim.x + threadIdx.x;   // 4194304 float4s
    float4 v = in[i];
    __half2 lo = __floats2half2_rn(v.x, v.y);
    __half2 hi = __floats2half2_rn(v.z, v.w);
    ((uint2*)g_Xh)[i] = make_uint2(*(uint32_t*)&lo, *(uint32_t*)&hi);
}
__global__ void cvt_w_kernel(const float4* __restrict__ in)
{
    int i = blockIdx.x * blockDim.x + threadIdx.x;   // 524288 float4s
    float4 v = in[i];
    __half2 lo = __floats2half2_rn(v.x, v.y);
    __half2 hi = __floats2half2_rn(v.z, v.w);
    ((uint2*)g_Wh)[i] = make_uint2(*(uint32_t*)&lo, *(uint32_t*)&hi);
}

// ---------------- kernel 1: fp16 GEMM (BM=128,BN=128,BK=64) + epilogue ------
// 256 threads = 8 warps in 2(M) x 4(N); warp tile 64x32 (m16n8k16 mma).
// smem bytes: [0,256) q; [256,2304) spart[4][128]; tiles @2560 + st*32768:
//   A 128 rows x 64 half (128B/row, XOR-swizzled 16B granules)  = 16KB
//   B  64 rows x 128 half (256B/row, XOR-swizzled 16B granules) = 16KB
#define STGB 32768
#define TILEB 2560

__global__ __launch_bounds__(256, 2)
void gemm_kernel(const float* __restrict__ Qk)
{
    extern __shared__ float smem[];
    const uint32_t sb = (uint32_t)__cvta_generic_to_shared(smem);
    const int tid = threadIdx.x, warp = tid >> 5, lane = tid & 31;
    const int nt = blockIdx.x;               // 0..15 (head)
    const int mt = blockIdx.y;               // 0..127
    const int m0 = mt << 7, n0 = nt << 7;

    // ---- copy plans (per stage: A 4x16B + B 4x16B per thread) ----
    uint32_t aoffb[4]; const __half* agp[4];
#pragma unroll
    for (int i = 0; i < 4; i++) {
        int ga = tid + i * 256, row = ga >> 3, g = ga & 7;   // 128 rows x 8 gran
        aoffb[i] = row * 128 + ((g ^ (row & 7)) << 4);
        agp[i]   = g_Xh + (size_t)(m0 + row) * TDIN + g * 8;
    }
    uint32_t boffb[4]; const __half* bgp[4];
#pragma unroll
    for (int i = 0; i < 4; i++) {
        int gb = tid + i * 256, row = gb >> 4, g = gb & 15;  // 64 rows x 16 gran
        boffb[i] = 16384 + row * 256 + ((g ^ (row & 7)) << 4);
        bgp[i]   = g_Wh + (size_t)row * 2048 + n0 + g * 8;
    }
    auto load_stage = [&](int st, int k0) {
        uint32_t base = sb + TILEB + st * STGB;
#pragma unroll
        for (int i = 0; i < 4; i++)
            asm volatile("cp.async.cg.shared.global [%0], [%1], 16;"
                         :: "r"(base + aoffb[i]), "l"(agp[i] + k0) : "memory");
#pragma unroll
        for (int i = 0; i < 4; i++)
            asm volatile("cp.async.cg.shared.global [%0], [%1], 16;"
                         :: "r"(base + boffb[i]), "l"(bgp[i] + (size_t)k0 * 2048) : "memory");
        asm volatile("cp.async.commit_group;" ::: "memory");
    };

    load_stage(0, 0);
    load_stage(1, 64);
    if (tid < 64) smem[tid] = Qk[(nt << 6) + tid];

    // fragment addressing
    const int wm = (warp >> 2) << 6;         // 0/64
    const int wc = warp & 3;                 // n quarter (32 halfs)
    const int arow = wm + (lane & 15);       // + mi*16
    const int aghi = lane >> 4;              // granule select within k16
    const int bkk = lane & 15;               // + ks*16
    const int bgn = (wc << 2) + (lane >> 4); // + np*2 (granule of 8 halfs)

    float acc[4][4][4];
#pragma unroll
    for (int a = 0; a < 4; a++)
#pragma unroll
        for (int b = 0; b < 4; b++)
#pragma unroll
            for (int c = 0; c < 4; c++) acc[a][b][c] = 0.f;

    for (int kt = 0; kt < 16; kt++) {        // 16 tiles of BK=64
        if (kt < 15) asm volatile("cp.async.wait_group 1;" ::: "memory");
        else         asm volatile("cp.async.wait_group 0;" ::: "memory");
        __syncthreads();
        if (kt + 2 < 16) load_stage((kt + 2) % 3, (kt + 2) << 6);

        const int cs = kt % 3;
        const uint32_t ab = sb + TILEB + cs * STGB;
        const uint32_t bb = ab + 16384;

#pragma unroll
        for (int ks = 0; ks < 4; ks++) {
            uint32_t afr[4][4];
#pragma unroll
            for (int mi = 0; mi < 4; mi++) {
                int r = arow + mi * 16;
                uint32_t addr = ab + r * 128 + ((((ks << 1) + aghi) ^ (r & 7)) << 4);
                asm volatile("ldmatrix.sync.aligned.m8n8.x4.shared.b16 {%0,%1,%2,%3}, [%4];"
                             : "=r"(afr[mi][0]), "=r"(afr[mi][1]),
                               "=r"(afr[mi][2]), "=r"(afr[mi][3]) : "r"(addr));
            }
            uint32_t bfr[2][4];
#pragma unroll
            for (int np = 0; np < 2; np++) {
                int kk = (ks << 4) + bkk;
                int gn = bgn + np * 2;
                uint32_t addr = bb + kk * 256 + ((gn ^ (kk & 7)) << 4);
                asm volatile("ldmatrix.sync.aligned.m8n8.x4.trans.shared.b16 {%0,%1,%2,%3}, [%4];"
                             : "=r"(bfr[np][0]), "=r"(bfr[np][1]),
                               "=r"(bfr[np][2]), "=r"(bfr[np][3]) : "r"(addr));
            }
#pragma unroll
            for (int mi = 0; mi < 4; mi++)
#pragma unroll
                for (int ni = 0; ni < 4; ni++) {
                    asm volatile("mma.sync.aligned.m16n8k16.row.col.f32.f16.f16.f32 "
                                 "{%0,%1,%2,%3}, {%4,%5,%6,%7}, {%8,%9}, {%0,%1,%2,%3};"
                                 : "+f"(acc[mi][ni][0]), "+f"(acc[mi][ni][1]),
                                   "+f"(acc[mi][ni][2]), "+f"(acc[mi][ni][3])
                                 : "r"(afr[mi][0]), "r"(afr[mi][1]),
                                   "r"(afr[mi][2]), "r"(afr[mi][3]),
                                   "r"(bfr[ni >> 1][(ni & 1) * 2]),
                                   "r"(bfr[ni >> 1][(ni & 1) * 2 + 1]));
                }
        }
    }

    // ---- epilogue: relu, V store [bh][d][t], s = sum_d q*relu(k) ----
    const int b = m0 >> 12, t0 = m0 & (TT - 1);
    const int bh = b * TH + nt;
    const int d0 = (wc << 4) + (lane & 3);
    float qv[4];
#pragma unroll
    for (int ni = 0; ni < 4; ni++) qv[ni] = smem[d0 + ni * 4];
    float* vbase = g_V + (size_t)bh * (64 * 4096);

#pragma unroll
    for (int mi = 0; mi < 4; mi++) {
#pragma unroll
        for (int hf = 0; hf < 2; hf++) {
            float sp = 0.f;
            const int row = wm + mi * 16 + (lane >> 2) + hf * 8;  // 0..127
#pragma unroll
            for (int ni = 0; ni < 4; ni++) {
                const int d = d0 + ni * 4;
                float kk = fmaxf(acc[mi][ni][hf * 2], 0.f);
                float vv = fmaxf(acc[mi][ni][hf * 2 + 1], 0.f);
                sp = fmaf(qv[ni], kk, sp);
                vbase[(size_t)d * 4096 + t0 + row] = vv;
            }
            sp += __shfl_xor_sync(0xffffffffu, sp, 1);
            sp += __shfl_xor_sync(0xffffffffu, sp, 2);
            if ((lane & 3) == 0) smem[64 + wc * 128 + row] = sp;
        }
    }
    __syncthreads();
    if (tid < 128) {
        float s = smem[64 + tid] + smem[64 + 128 + tid]
                + smem[64 + 256 + tid] + smem[64 + 384 + tid];
        g_S[(size_t)bh * TT + t0 + tid] = s;
    }
}

// ---------------- kernel 2: chunk E/W partials + in-block exclusive scan ----
__global__ __launch_bounds__(256) void chunk_kernel()
{
    __shared__ float es[TT];          // 16KB: exp(s)
    __shared__ float ws[NC][TD];      // 16KB: chunk e*v sums
    __shared__ float eagg[NC];
    const int bh = blockIdx.x, tid = threadIdx.x;
    const int lane = tid & 31, w = tid >> 5;

    const float* sp = g_S + (size_t)bh * TT;
    for (int i = tid; i < TT; i += 256) es[i] = __expf(sp[i]);
    __syncthreads();

    for (int c = w; c < NC; c += 8) {
        float e = es[c * CT + lane] + es[c * CT + 32 + lane];
#pragma unroll
        for (int o = 16; o; o >>= 1) e += __shfl_xor_sync(0xffffffffu, e, o);
        if (lane == 0) eagg[c] = e;
    }

    const int d = tid & 63;
    const float* vrow = g_V + ((size_t)bh * 64 + d) * 4096;
    for (int cg = 0; cg < 16; cg++) {
        int ch = (tid >> 6) + cg * 4;
        const float4* vp4 = (const float4*)(vrow + ch * CT);
        float wv = 0.f;
#pragma unroll
        for (int j = 0; j < 16; j++) {
            float4 v = vp4[j];
            wv = fmaf(es[ch * CT + 4 * j],     v.x, wv);
            wv = fmaf(es[ch * CT + 4 * j + 1], v.y, wv);
            wv = fmaf(es[ch * CT + 4 * j + 2], v.z, wv);
            wv = fmaf(es[ch * CT + 4 * j + 3], v.w, wv);
        }
        ws[ch][d] = wv;
    }
    __syncthreads();

    if (tid < 64) {
        float a = 0.f;
#pragma unroll
        for (int c = 0; c < NC; c++) {
            float t = ws[c][tid];
            g_W[((size_t)bh * NC + c) * TD + tid] = a;
            a += t;
        }
    } else if (tid == 64) {
        float a = 0.f;
#pragma unroll
        for (int c = 0; c < NC; c++) {
            float t = eagg[c];
            g_E[bh * NC + c] = a;
            a += t;
        }
    }
}

// ---------------- kernel 3: local scan + head-sum -> out --------------------
__global__ __launch_bounds__(1024) void final_kernel(float* __restrict__ out)
{
    __shared__ float es_s[1024], rc_s[1024], p_s[16 * 4 * 64], wtot[16];
    const int ch = blockIdx.x, b = blockIdx.y, tid = threadIdx.x;
    const int h = tid >> 6, t = tid & 63, lane = tid & 31, uh = (tid >> 5) & 1;
    const int bh = b * TH + h;

    float e = __expf(g_S[(size_t)bh * TT + ch * CT + t]);
    es_s[tid] = e;
    float p = e;
#pragma unroll
    for (int o = 1; o < 32; o <<= 1) {
        float x = __shfl_up_sync(0xffffffffu, p, o);
        if (lane >= o) p += x;
    }
    if (lane == 31 && uh == 0) wtot[h] = p;
    __syncthreads();
    float pref = p + (uh ? wtot[h] : 0.f);
    rc_s[tid] = 1.0f / (g_E[bh * NC + ch] + pref);
    __syncthreads();

    const int d = t;                                 // phase B mapping
    float a = g_W[((size_t)bh * NC + ch) * TD + d];  // exclusive prefix
    const float4* vp4 = (const float4*)(g_V + ((size_t)bh * 64 + d) * 4096 + ch * CT);
    float* outb = out + ((size_t)b * TT + ch * CT) * TD;

    for (int g4 = 0; g4 < 16; g4++) {
        float4 v = vp4[g4];
        a = fmaf(es_s[h * 64 + g4 * 4 + 0], v.x, a);
        p_s[(h * 4 + 0) * 64 + d] = a * rc_s[h * 64 + g4 * 4 + 0];
        a = fmaf(es_s[h * 64 + g4 * 4 + 1], v.y, a);
        p_s[(h * 4 + 1) * 64 + d] = a * rc_s[h * 64 + g4 * 4 + 1];
        a = fmaf(es_s[h * 64 + g4 * 4 + 2], v.z, a);
        p_s[(h * 4 + 2) * 64 + d] = a * rc_s[h * 64 + g4 * 4 + 2];
        a = fmaf(es_s[h * 64 + g4 * 4 + 3], v.w, a);
        p_s[(h * 4 + 3) * 64 + d] = a * rc_s[h * 64 + g4 * 4 + 3];
        __syncthreads();
        if (tid < 256) {
            int tt = tid >> 6, dd = tid & 63;
            float s = 0.f;
#pragma unroll
            for (int hh = 0; hh < 16; hh++) s += p_s[(hh * 4 + tt) * 64 + dd];
            outb[(size_t)(g4 * 4 + tt) * TD + dd] = s;
        }
        __syncthreads();
    }
}

// ---------------- launch ----------------------------------------------------
extern "C" void kernel_launch(void* const* d_in, const int* in_sizes, int n_in,
                              void* d_out, int out_size)
{
    const float* x = (const float*)d_in[0];   // inputs    [4,4096,1024]
    const float* w = (const float*)d_in[1];   // kv_kernel [1024,16,64,2]
    const float* q = (const float*)d_in[2];   // q_kernel  [16,64]
    float* out = (float*)d_out;               // [4,4096,64] f32

    cvt_x_kernel<<<4194304 / 256, 256>>>((const float4*)x);
    cvt_w_kernel<<<524288  / 256, 256>>>((const float4*)w);

    cudaFuncSetAttribute(gemm_kernel,
                         cudaFuncAttributeMaxDynamicSharedMemorySize, 100864);
    gemm_kernel<<<dim3(16, 128), 256, 100864>>>(q);

    chunk_kernel<<<64, 256>>>();
    final_kernel<<<dim3(NC, TB), 1024>>>(out);
}

// round 10
// speedup vs baseline: 1.6977x; 1.0946x over previous
#include <cuda_runtime.h>
#include <cuda_fp16.h>
#include <cstdint>

// Problem dims (fixed): B=4, T=4096, D_IN=1024, H=16, D=64
#define TB 4
#define TT 4096
#define TDIN 1024
#define TH 16
#define TD 64
#define NC 64     // chunks per (b,h)
#define CT 64     // timesteps per chunk

// ---------------- scratch ----------------------------------------------------
__device__ __half g_Xh[16384ull * 1024];    // fp16 X [m][k]              (32 MB)
__device__ __half g_Wh[1024ull * 2048];     // fp16 W [k][n]              ( 4 MB)
__device__ float  g_V [64ull * 64 * 4096];  // v[bh][d][t]                (64 MB)
__device__ float  g_S [64ull * 4096];       // s[bh][t]                   ( 1 MB)
__device__ float  g_E [64 * NC];            // chunk e-sums -> excl prefix
__device__ float  g_W [64ull * NC * TD];    // chunk e*v sums -> excl prefix

// ---------------- kernel 0: convert inputs to fp16 --------------------------
__global__ void cvt_x_kernel(const float4* __restrict__ in)
{
    int i = blockIdx.x * blockDim.x + threadIdx.x;   // 4194304 float4s
    float4 v = in[i];
    __half2 lo = __floats2half2_rn(v.x, v.y);
    __half2 hi = __floats2half2_rn(v.z, v.w);
    ((uint2*)g_Xh)[i] = make_uint2(*(uint32_t*)&lo, *(uint32_t*)&hi);
}
__global__ void cvt_w_kernel(const float4* __restrict__ in)
{
    int i = blockIdx.x * blockDim.x + threadIdx.x;   // 524288 float4s
    float4 v = in[i];
    __half2 lo = __floats2half2_rn(v.x, v.y);
    __half2 hi = __floats2half2_rn(v.z, v.w);
    ((uint2*)g_Wh)[i] = make_uint2(*(uint32_t*)&lo, *(uint32_t*)&hi);
}

// ---------------- kernel 1: fp16 GEMM (BM=128,BN=128,BK=64) + epilogue ------
// (unchanged from R8 — measured ~155us)
#define STGB 32768
#define TILEB 2560

__global__ __launch_bounds__(256, 2)
void gemm_kernel(const float* __restrict__ Qk)
{
    extern __shared__ float smem[];
    const uint32_t sb = (uint32_t)__cvta_generic_to_shared(smem);
    const int tid = threadIdx.x, warp = tid >> 5, lane = tid & 31;
    const int nt = blockIdx.x;               // 0..15 (head)
    const int mt = blockIdx.y;               // 0..127
    const int m0 = mt << 7, n0 = nt << 7;

    uint32_t aoffb[4]; const __half* agp[4];
#pragma unroll
    for (int i = 0; i < 4; i++) {
        int ga = tid + i * 256, row = ga >> 3, g = ga & 7;   // 128 rows x 8 gran
        aoffb[i] = row * 128 + ((g ^ (row & 7)) << 4);
        agp[i]   = g_Xh + (size_t)(m0 + row) * TDIN + g * 8;
    }
    uint32_t boffb[4]; const __half* bgp[4];
#pragma unroll
    for (int i = 0; i < 4; i++) {
        int gb = tid + i * 256, row = gb >> 4, g = gb & 15;  // 64 rows x 16 gran
        boffb[i] = 16384 + row * 256 + ((g ^ (row & 7)) << 4);
        bgp[i]   = g_Wh + (size_t)row * 2048 + n0 + g * 8;
    }
    auto load_stage = [&](int st, int k0) {
        uint32_t base = sb + TILEB + st * STGB;
#pragma unroll
        for (int i = 0; i < 4; i++)
            asm volatile("cp.async.cg.shared.global [%0], [%1], 16;"
                         :: "r"(base + aoffb[i]), "l"(agp[i] + k0) : "memory");
#pragma unroll
        for (int i = 0; i < 4; i++)
            asm volatile("cp.async.cg.shared.global [%0], [%1], 16;"
                         :: "r"(base + boffb[i]), "l"(bgp[i] + (size_t)k0 * 2048) : "memory");
        asm volatile("cp.async.commit_group;" ::: "memory");
    };

    load_stage(0, 0);
    load_stage(1, 64);
    if (tid < 64) smem[tid] = Qk[(nt << 6) + tid];

    const int wm = (warp >> 2) << 6;         // 0/64
    const int wc = warp & 3;                 // n quarter (32 halfs)
    const int arow = wm + (lane & 15);
    const int aghi = lane >> 4;
    const int bkk = lane & 15;
    const int bgn = (wc << 2) + (lane >> 4);

    float acc[4][4][4];
#pragma unroll
    for (int a = 0; a < 4; a++)
#pragma unroll
        for (int b = 0; b < 4; b++)
#pragma unroll
            for (int c = 0; c < 4; c++) acc[a][b][c] = 0.f;

    for (int kt = 0; kt < 16; kt++) {        // 16 tiles of BK=64
        if (kt < 15) asm volatile("cp.async.wait_group 1;" ::: "memory");
        else         asm volatile("cp.async.wait_group 0;" ::: "memory");
        __syncthreads();
        if (kt + 2 < 16) load_stage((kt + 2) % 3, (kt + 2) << 6);

        const int cs = kt % 3;
        const uint32_t ab = sb + TILEB + cs * STGB;
        const uint32_t bb = ab + 16384;

#pragma unroll
        for (int ks = 0; ks < 4; ks++) {
            uint32_t afr[4][4];
#pragma unroll
            for (int mi = 0; mi < 4; mi++) {
                int r = arow + mi * 16;
                uint32_t addr = ab + r * 128 + ((((ks << 1) + aghi) ^ (r & 7)) << 4);
                asm volatile("ldmatrix.sync.aligned.m8n8.x4.shared.b16 {%0,%1,%2,%3}, [%4];"
                             : "=r"(afr[mi][0]), "=r"(afr[mi][1]),
                               "=r"(afr[mi][2]), "=r"(afr[mi][3]) : "r"(addr));
            }
            uint32_t bfr[2][4];
#pragma unroll
            for (int np = 0; np < 2; np++) {
                int kk = (ks << 4) + bkk;
                int gn = bgn + np * 2;
                uint32_t addr = bb + kk * 256 + ((gn ^ (kk & 7)) << 4);
                asm volatile("ldmatrix.sync.aligned.m8n8.x4.trans.shared.b16 {%0,%1,%2,%3}, [%4];"
                             : "=r"(bfr[np][0]), "=r"(bfr[np][1]),
                               "=r"(bfr[np][2]), "=r"(bfr[np][3]) : "r"(addr));
            }
#pragma unroll
            for (int mi = 0; mi < 4; mi++)
#pragma unroll
                for (int ni = 0; ni < 4; ni++) {
                    asm volatile("mma.sync.aligned.m16n8k16.row.col.f32.f16.f16.f32 "
                                 "{%0,%1,%2,%3}, {%4,%5,%6,%7}, {%8,%9}, {%0,%1,%2,%3};"
                                 : "+f"(acc[mi][ni][0]), "+f"(acc[mi][ni][1]),
                                   "+f"(acc[mi][ni][2]), "+f"(acc[mi][ni][3])
                                 : "r"(afr[mi][0]), "r"(afr[mi][1]),
                                   "r"(afr[mi][2]), "r"(afr[mi][3]),
                                   "r"(bfr[ni >> 1][(ni & 1) * 2]),
                                   "r"(bfr[ni >> 1][(ni & 1) * 2 + 1]));
                }
        }
    }

    // ---- epilogue: relu, V store [bh][d][t], s = sum_d q*relu(k) ----
    const int b = m0 >> 12, t0 = m0 & (TT - 1);
    const int bh = b * TH + nt;
    const int d0 = (wc << 4) + (lane & 3);
    float qv[4];
#pragma unroll
    for (int ni = 0; ni < 4; ni++) qv[ni] = smem[d0 + ni * 4];
    float* vbase = g_V + (size_t)bh * (64 * 4096);

#pragma unroll
    for (int mi = 0; mi < 4; mi++) {
#pragma unroll
        for (int hf = 0; hf < 2; hf++) {
            float sp = 0.f;
            const int row = wm + mi * 16 + (lane >> 2) + hf * 8;  // 0..127
#pragma unroll
            for (int ni = 0; ni < 4; ni++) {
                const int d = d0 + ni * 4;
                float kk = fmaxf(acc[mi][ni][hf * 2], 0.f);
                float vv = fmaxf(acc[mi][ni][hf * 2 + 1], 0.f);
                sp = fmaf(qv[ni], kk, sp);
                vbase[(size_t)d * 4096 + t0 + row] = vv;
            }
            sp += __shfl_xor_sync(0xffffffffu, sp, 1);
            sp += __shfl_xor_sync(0xffffffffu, sp, 2);
            if ((lane & 3) == 0) smem[64 + wc * 128 + row] = sp;
        }
    }
    __syncthreads();
    if (tid < 128) {
        float s = smem[64 + tid] + smem[64 + 128 + tid]
                + smem[64 + 256 + tid] + smem[64 + 384 + tid];
        g_S[(size_t)bh * TT + t0 + tid] = s;
    }
}

// ---------------- kernel 2a: chunk partials (512 blocks, full chip) ---------
// Block (p, bh): 512 timesteps [p*512, p*512+512) = 8 chunks.
// Writes UNSCANNED E and W partials; scanagg turns them into excl prefixes.
__global__ __launch_bounds__(256) void partial_kernel()
{
    __shared__ float es[512];
    const int p = blockIdx.x, bh = blockIdx.y, tid = threadIdx.x;
    const int lane = tid & 31, w = tid >> 5;
    const int tbase = p * 512;

    const float* sp = g_S + (size_t)bh * TT + tbase;
    for (int i = tid; i < 512; i += 256) es[i] = __expf(sp[i]);
    __syncthreads();

    // E for chunk w (one chunk per warp)
    {
        float e = es[w * CT + lane] + es[w * CT + 32 + lane];
#pragma unroll
        for (int o = 16; o; o >>= 1) e += __shfl_xor_sync(0xffffffffu, e, o);
        if (lane == 0) g_E[bh * NC + p * 8 + w] = e;
    }

    // W for (chunk, d): thread = (cg = tid>>6 in 0..3, d = tid&63), 2 chunks each
    const int d = tid & 63;
    const float* vrow = g_V + ((size_t)bh * 64 + d) * 4096 + tbase;
#pragma unroll
    for (int cg2 = 0; cg2 < 2; cg2++) {
        int ch = (tid >> 6) + cg2 * 4;       // local chunk 0..7
        const float4* vp4 = (const float4*)(vrow + ch * CT);
        float wv = 0.f;
#pragma unroll
        for (int j = 0; j < 16; j++) {
            float4 v = vp4[j];
            wv = fmaf(es[ch * CT + 4 * j],     v.x, wv);
            wv = fmaf(es[ch * CT + 4 * j + 1], v.y, wv);
            wv = fmaf(es[ch * CT + 4 * j + 2], v.z, wv);
            wv = fmaf(es[ch * CT + 4 * j + 3], v.w, wv);
        }
        g_W[((size_t)bh * NC + p * 8 + ch) * TD + d] = wv;
    }
}

// ---------------- kernel 2b: exclusive scan of chunk aggregates -------------
// Batched loads (full MLP), prefix in registers, store all.
__global__ void scanagg_kernel()
{
    const int bh = blockIdx.x, d = threadIdx.x;      // 64 threads
    float* wp = g_W + (size_t)bh * NC * TD + d;
    float v[NC];
#pragma unroll
    for (int c = 0; c < NC; c++) v[c] = wp[(size_t)c * TD];
    float aw = 0.f;
#pragma unroll
    for (int c = 0; c < NC; c++) { float t = v[c]; v[c] = aw; aw += t; }
#pragma unroll
    for (int c = 0; c < NC; c++) wp[(size_t)c * TD] = v[c];

    if (d == 0) {
        float* ep = g_E + bh * NC;
        float e[NC];
#pragma unroll
        for (int c = 0; c < NC; c++) e[c] = ep[c];
        float ae = 0.f;
#pragma unroll
        for (int c = 0; c < NC; c++) { float t = e[c]; e[c] = ae; ae += t; }
#pragma unroll
        for (int c = 0; c < NC; c++) ep[c] = e[c];
    }
}

// ---------------- kernel 3: local scan + head-sum -> out --------------------
// 8 t-steps per reduction round (half the syncs of R8).
__global__ __launch_bounds__(1024) void final_kernel(float* __restrict__ out)
{
    __shared__ float es_s[1024], rc_s[1024], p_s[16 * 8 * 64], wtot[16];
    const int ch = blockIdx.x, b = blockIdx.y, tid = threadIdx.x;
    const int h = tid >> 6, t = tid & 63, lane = tid & 31, uh = (tid >> 5) & 1;
    const int bh = b * TH + h;

    float e = __expf(g_S[(size_t)bh * TT + ch * CT + t]);
    es_s[tid] = e;
    float p = e;
#pragma unroll
    for (int o = 1; o < 32; o <<= 1) {
        float x = __shfl_up_sync(0xffffffffu, p, o);
        if (lane >= o) p += x;
    }
    if (lane == 31 && uh == 0) wtot[h] = p;
    __syncthreads();
    float pref = p + (uh ? wtot[h] : 0.f);
    rc_s[tid] = 1.0f / (g_E[bh * NC + ch] + pref);
    __syncthreads();

    const int d = t;                                 // phase B mapping
    float a = g_W[((size_t)bh * NC + ch) * TD + d];  // exclusive prefix
    const float4* vp4 = (const float4*)(g_V + ((size_t)bh * 64 + d) * 4096 + ch * CT);
    float* outb = out + ((size_t)b * TT + ch * CT) * TD;

#pragma unroll
    for (int g8 = 0; g8 < 8; g8++) {
        float4 v0 = vp4[2 * g8], v1 = vp4[2 * g8 + 1];
        const int te = h * 64 + g8 * 8;
        a = fmaf(es_s[te + 0], v0.x, a); p_s[(h * 8 + 0) * 64 + d] = a * rc_s[te + 0];
        a = fmaf(es_s[te + 1], v0.y, a); p_s[(h * 8 + 1) * 64 + d] = a * rc_s[te + 1];
        a = fmaf(es_s[te + 2], v0.z, a); p_s[(h * 8 + 2) * 64 + d] = a * rc_s[te + 2];
        a = fmaf(es_s[te + 3], v0.w, a); p_s[(h * 8 + 3) * 64 + d] = a * rc_s[te + 3];
        a = fmaf(es_s[te + 4], v1.x, a); p_s[(h * 8 + 4) * 64 + d] = a * rc_s[te + 4];
        a = fmaf(es_s[te + 5], v1.y, a); p_s[(h * 8 + 5) * 64 + d] = a * rc_s[te + 5];
        a = fmaf(es_s[te + 6], v1.z, a); p_s[(h * 8 + 6) * 64 + d] = a * rc_s[te + 6];
        a = fmaf(es_s[te + 7], v1.w, a); p_s[(h * 8 + 7) * 64 + d] = a * rc_s[te + 7];
        __syncthreads();
        if (tid < 512) {
            int tt = tid >> 6, dd = tid & 63;
            float s = 0.f;
#pragma unroll
            for (int hh = 0; hh < 16; hh++) s += p_s[(hh * 8 + tt) * 64 + dd];
            outb[(size_t)(g8 * 8 + tt) * TD + dd] = s;
        }
        __syncthreads();
    }
}

// ---------------- launch ----------------------------------------------------
extern "C" void kernel_launch(void* const* d_in, const int* in_sizes, int n_in,
                              void* d_out, int out_size)
{
    const float* x = (const float*)d_in[0];   // inputs    [4,4096,1024]
    const float* w = (const float*)d_in[1];   // kv_kernel [1024,16,64,2]
    const float* q = (const float*)d_in[2];   // q_kernel  [16,64]
    float* out = (float*)d_out;               // [4,4096,64] f32

    cvt_x_kernel<<<4194304 / 256, 256>>>((const float4*)x);
    cvt_w_kernel<<<524288  / 256, 256>>>((const float4*)w);

    cudaFuncSetAttribute(gemm_kernel,
                         cudaFuncAttributeMaxDynamicSharedMemorySize, 100864);
    gemm_kernel<<<dim3(16, 128), 256, 100864>>>(q);

    partial_kernel<<<dim3(8, 64), 256>>>();
    scanagg_kernel<<<64, TD>>>();
    final_kernel<<<dim3(NC, TB), 1024>>>(out);
}

// round 12
// speedup vs baseline: 1.8355x; 1.0812x over previous
#include <cuda_runtime.h>
#include <cuda_fp16.h>
#include <cstdint>

// Problem dims (fixed): B=4, T=4096, D_IN=1024, H=16, D=64
#define TB 4
#define TT 4096
#define TDIN 1024
#define TH 16
#define TD 64
#define NC 64     // chunks per (b,h)
#define CT 64     // timesteps per chunk

// ---------------- scratch ----------------------------------------------------
__device__ __half g_Xh[16384ull * 1024];    // fp16 X [m][k]              (32 MB)
__device__ __half g_Wh[1024ull * 2048];     // fp16 W [k][n]              ( 4 MB)
__device__ __half g_Vh[64ull * 64 * 4096];  // fp16 v[bh][d][t]           (32 MB)
__device__ float  g_S [64ull * 4096];       // s[bh][t]                   ( 1 MB)
__device__ float  g_E [64 * NC];            // chunk e-sums -> excl prefix
__device__ float  g_W [64ull * NC * TD];    // chunk e*v sums -> excl prefix

// ---------------- kernel 0: convert X and W to fp16 (single launch) ---------
#define NX4 4194304            // float4s in X
#define NW4 524288             // float4s in W
__global__ void cvt_kernel(const float4* __restrict__ x, const float4* __restrict__ w)
{
    int i = blockIdx.x * blockDim.x + threadIdx.x;   // 0 .. NX4+NW4-1
    float4 v;
    if (i < NX4) v = x[i];
    else         v = w[i - NX4];
    __half2 lo = __floats2half2_rn(v.x, v.y);
    __half2 hi = __floats2half2_rn(v.z, v.w);
    uint2 pk = make_uint2(*(uint32_t*)&lo, *(uint32_t*)&hi);
    if (i < NX4) ((uint2*)g_Xh)[i] = pk;
    else         ((uint2*)g_Wh)[i - NX4] = pk;
}

// ---------------- kernel 1: fp16 GEMM (BM=128,BN=128,BK=64) + epilogue ------
#define STGB 32768
#define TILEB 2560

__global__ __launch_bounds__(256, 2)
void gemm_kernel(const float* __restrict__ Qk)
{
    extern __shared__ float smem[];
    const uint32_t sb = (uint32_t)__cvta_generic_to_shared(smem);
    const int tid = threadIdx.x, warp = tid >> 5, lane = tid & 31;
    const int nt = blockIdx.x;               // 0..15 (head)
    const int mt = blockIdx.y;               // 0..127
    const int m0 = mt << 7, n0 = nt << 7;

    uint32_t aoffb[4]; const __half* agp[4];
#pragma unroll
    for (int i = 0; i < 4; i++) {
        int ga = tid + i * 256, row = ga >> 3, g = ga & 7;   // 128 rows x 8 gran
        aoffb[i] = row * 128 + ((g ^ (row & 7)) << 4);
        agp[i]   = g_Xh + (size_t)(m0 + row) * TDIN + g * 8;
    }
    uint32_t boffb[4]; const __half* bgp[4];
#pragma unroll
    for (int i = 0; i < 4; i++) {
        int gb = tid + i * 256, row = gb >> 4, g = gb & 15;  // 64 rows x 16 gran
        boffb[i] = 16384 + row * 256 + ((g ^ (row & 7)) << 4);
        bgp[i]   = g_Wh + (size_t)row * 2048 + n0 + g * 8;
    }
    auto load_stage = [&](int st, int k0) {
        uint32_t base = sb + TILEB + st * STGB;
#pragma unroll
        for (int i = 0; i < 4; i++)
            asm volatile("cp.async.cg.shared.global [%0], [%1], 16;"
                         :: "r"(base + aoffb[i]), "l"(agp[i] + k0) : "memory");
#pragma unroll
        for (int i = 0; i < 4; i++)
            asm volatile("cp.async.cg.shared.global [%0], [%1], 16;"
                         :: "r"(base + boffb[i]), "l"(bgp[i] + (size_t)k0 * 2048) : "memory");
        asm volatile("cp.async.commit_group;" ::: "memory");
    };

    load_stage(0, 0);
    load_stage(1, 64);
    if (tid < 64) smem[tid] = Qk[(nt << 6) + tid];

    const int wm = (warp >> 2) << 6;         // 0/64
    const int wc = warp & 3;                 // n quarter (32 halfs)
    const int arow = wm + (lane & 15);
    const int aghi = lane >> 4;
    const int bkk = lane & 15;
    const int bgn = (wc << 2) + (lane >> 4);

    float acc[4][4][4];
#pragma unroll
    for (int a = 0; a < 4; a++)
#pragma unroll
        for (int b = 0; b < 4; b++)
#pragma unroll
            for (int c = 0; c < 4; c++) acc[a][b][c] = 0.f;

    for (int kt = 0; kt < 16; kt++) {        // 16 tiles of BK=64
        if (kt < 15) asm volatile("cp.async.wait_group 1;" ::: "memory");
        else         asm volatile("cp.async.wait_group 0;" ::: "memory");
        __syncthreads();
        if (kt + 2 < 16) load_stage((kt + 2) % 3, (kt + 2) << 6);

        const int cs = kt % 3;
        const uint32_t ab = sb + TILEB + cs * STGB;
        const uint32_t bb = ab + 16384;

#pragma unroll
        for (int ks = 0; ks < 4; ks++) {
            uint32_t afr[4][4];
#pragma unroll
            for (int mi = 0; mi < 4; mi++) {
                int r = arow + mi * 16;
                uint32_t addr = ab + r * 128 + ((((ks << 1) + aghi) ^ (r & 7)) << 4);
                asm volatile("ldmatrix.sync.aligned.m8n8.x4.shared.b16 {%0,%1,%2,%3}, [%4];"
                             : "=r"(afr[mi][0]), "=r"(afr[mi][1]),
                               "=r"(afr[mi][2]), "=r"(afr[mi][3]) : "r"(addr));
            }
            uint32_t bfr[2][4];
#pragma unroll
            for (int np = 0; np < 2; np++) {
                int kk = (ks << 4) + bkk;
                int gn = bgn + np * 2;
                uint32_t addr = bb + kk * 256 + ((gn ^ (kk & 7)) << 4);
                asm volatile("ldmatrix.sync.aligned.m8n8.x4.trans.shared.b16 {%0,%1,%2,%3}, [%4];"
                             : "=r"(bfr[np][0]), "=r"(bfr[np][1]),
                               "=r"(bfr[np][2]), "=r"(bfr[np][3]) : "r"(addr));
            }
#pragma unroll
            for (int mi = 0; mi < 4; mi++)
#pragma unroll
                for (int ni = 0; ni < 4; ni++) {
                    asm volatile("mma.sync.aligned.m16n8k16.row.col.f32.f16.f16.f32 "
                                 "{%0,%1,%2,%3}, {%4,%5,%6,%7}, {%8,%9}, {%0,%1,%2,%3};"
                                 : "+f"(acc[mi][ni][0]), "+f"(acc[mi][ni][1]),
                                   "+f"(acc[mi][ni][2]), "+f"(acc[mi][ni][3])
                                 : "r"(afr[mi][0]), "r"(afr[mi][1]),
                                   "r"(afr[mi][2]), "r"(afr[mi][3]),
                                   "r"(bfr[ni >> 1][(ni & 1) * 2]),
                                   "r"(bfr[ni >> 1][(ni & 1) * 2 + 1]));
                }
        }
    }

    // ---- epilogue: relu, V store fp16 [bh][d][t], s = sum_d q*relu(k) ----
    const int b = m0 >> 12, t0 = m0 & (TT - 1);
    const int bh = b * TH + nt;
    const int d0 = (wc << 4) + (lane & 3);
    float qv[4];
#pragma unroll
    for (int ni = 0; ni < 4; ni++) qv[ni] = smem[d0 + ni * 4];
    __half* vbase = g_Vh + (size_t)bh * (64 * 4096);

#pragma unroll
    for (int mi = 0; mi < 4; mi++) {
#pragma unroll
        for (int hf = 0; hf < 2; hf++) {
            float sp = 0.f;
            const int row = wm + mi * 16 + (lane >> 2) + hf * 8;  // 0..127
#pragma unroll
            for (int ni = 0; ni < 4; ni++) {
                const int d = d0 + ni * 4;
                float kk = fmaxf(acc[mi][ni][hf * 2], 0.f);
                float vv = fmaxf(acc[mi][ni][hf * 2 + 1], 0.f);
                sp = fmaf(qv[ni], kk, sp);
                vbase[(size_t)d * 4096 + t0 + row] = __float2half_rn(vv);
            }
            sp += __shfl_xor_sync(0xffffffffu, sp, 1);
            sp += __shfl_xor_sync(0xffffffffu, sp, 2);
            if ((lane & 3) == 0) smem[64 + wc * 128 + row] = sp;
        }
    }
    __syncthreads();
    if (tid < 128) {
        float s = smem[64 + tid] + smem[64 + 128 + tid]
                + smem[64 + 256 + tid] + smem[64 + 384 + tid];
        g_S[(size_t)bh * TT + t0 + tid] = s;
    }
}

// ---------------- kernel 2a: chunk partials (1024 blocks) -------------------
// Block (p, bh): 256 timesteps = 4 chunks. Writes UNSCANNED E/W partials.
__global__ __launch_bounds__(256) void partial_kernel()
{
    __shared__ float es[256];
    const int p = blockIdx.x, bh = blockIdx.y, tid = threadIdx.x;
    const int lane = tid & 31, w = tid >> 5;
    const int tbase = p * 256;

    es[tid] = __expf(g_S[(size_t)bh * TT + tbase + tid]);
    __syncthreads();

    if (w < 4) {     // E for chunk w
        float e = es[w * CT + lane] + es[w * CT + 32 + lane];
#pragma unroll
        for (int o = 16; o; o >>= 1) e += __shfl_xor_sync(0xffffffffu, e, o);
        if (lane == 0) g_E[bh * NC + p * 4 + w] = e;
    }

    // W for (chunk ch = tid>>6, d = tid&63)
    const int d = tid & 63, ch = tid >> 6;
    const uint4* vph = (const uint4*)(g_Vh + ((size_t)bh * 64 + d) * 4096
                                      + tbase + ch * CT);
    float wv = 0.f;
#pragma unroll
    for (int j = 0; j < 8; j++) {
        uint4 u = vph[j];
        const __half2* hp = (const __half2*)&u;
        float2 f0 = __half22float2(hp[0]);
        float2 f1 = __half22float2(hp[1]);
        float2 f2 = __half22float2(hp[2]);
        float2 f3 = __half22float2(hp[3]);
        const int e0 = ch * CT + j * 8;
        wv = fmaf(es[e0 + 0], f0.x, wv);
        wv = fmaf(es[e0 + 1], f0.y, wv);
        wv = fmaf(es[e0 + 2], f1.x, wv);
        wv = fmaf(es[e0 + 3], f1.y, wv);
        wv = fmaf(es[e0 + 4], f2.x, wv);
        wv = fmaf(es[e0 + 5], f2.y, wv);
        wv = fmaf(es[e0 + 6], f3.x, wv);
        wv = fmaf(es[e0 + 7], f3.y, wv);
    }
    g_W[((size_t)bh * NC + p * 4 + ch) * TD + d] = wv;
}

// ---------------- kernel 2b: exclusive scan of chunk aggregates -------------
__global__ void scanagg_kernel()
{
    const int bh = blockIdx.x, d = threadIdx.x;      // 64 threads
    float* wp = g_W + (size_t)bh * NC * TD + d;
    float v[NC];
#pragma unroll
    for (int c = 0; c < NC; c++) v[c] = wp[(size_t)c * TD];
    float aw = 0.f;
#pragma unroll
    for (int c = 0; c < NC; c++) { float t = v[c]; v[c] = aw; aw += t; }
#pragma unroll
    for (int c = 0; c < NC; c++) wp[(size_t)c * TD] = v[c];

    if (d == 0) {
        float* ep = g_E + bh * NC;
        float e[NC];
#pragma unroll
        for (int c = 0; c < NC; c++) e[c] = ep[c];
        float ae = 0.f;
#pragma unroll
        for (int c = 0; c < NC; c++) { float t = e[c]; e[c] = ae; ae += t; }
#pragma unroll
        for (int c = 0; c < NC; c++) ep[c] = e[c];
    }
}

// ---------------- kernel 3: local scan + head-sum -> out --------------------
__global__ __launch_bounds__(1024) void final_kernel(float* __restrict__ out)
{
    __shared__ float es_s[1024], rc_s[1024], p_s[16 * 8 * 64], wtot[16];
    const int ch = blockIdx.x, b = blockIdx.y, tid = threadIdx.x;
    const int h = tid >> 6, t = tid & 63, lane = tid & 31, uh = (tid >> 5) & 1;
    const int bh = b * TH + h;

    float e = __expf(g_S[(size_t)bh * TT + ch * CT + t]);
    es_s[tid] = e;
    float p = e;
#pragma unroll
    for (int o = 1; o < 32; o <<= 1) {
        float x = __shfl_up_sync(0xffffffffu, p, o);
        if (lane >= o) p += x;
    }
    if (lane == 31 && uh == 0) wtot[h] = p;
    __syncthreads();
    float pref = p + (uh ? wtot[h] : 0.f);
    rc_s[tid] = 1.0f / (g_E[bh * NC + ch] + pref);
    __syncthreads();

    const int d = t;                                 // phase B mapping
    float a = g_W[((size_t)bh * NC + ch) * TD + d];  // exclusive prefix
    const uint4* vph = (const uint4*)(g_Vh + ((size_t)bh * 64 + d) * 4096 + ch * CT);
    float* outb = out + ((size_t)b * TT + ch * CT) * TD;

#pragma unroll
    for (int g8 = 0; g8 < 8; g8++) {
        uint4 u = vph[g8];
        const __half2* hp = (const __half2*)&u;
        float2 f0 = __half22float2(hp[0]);
        float2 f1 = __half22float2(hp[1]);
        float2 f2 = __half22float2(hp[2]);
        float2 f3 = __half22float2(hp[3]);
        const int te = h * 64 + g8 * 8;
        a = fmaf(es_s[te + 0], f0.x, a); p_s[(h * 8 + 0) * 64 + d] = a * rc_s[te + 0];
        a = fmaf(es_s[te + 1], f0.y, a); p_s[(h * 8 + 1) * 64 + d] = a * rc_s[te + 1];
        a = fmaf(es_s[te + 2], f1.x, a); p_s[(h * 8 + 2) * 64 + d] = a * rc_s[te + 2];
        a = fmaf(es_s[te + 3], f1.y, a); p_s[(h * 8 + 3) * 64 + d] = a * rc_s[te + 3];
        a = fmaf(es_s[te + 4], f2.x, a); p_s[(h * 8 + 4) * 64 + d] = a * rc_s[te + 4];
        a = fmaf(es_s[te + 5], f2.y, a); p_s[(h * 8 + 5) * 64 + d] = a * rc_s[te + 5];
        a = fmaf(es_s[te + 6], f3.x, a); p_s[(h * 8 + 6) * 64 + d] = a * rc_s[te + 6];
        a = fmaf(es_s[te + 7], f3.y, a); p_s[(h * 8 + 7) * 64 + d] = a * rc_s[te + 7];
        __syncthreads();
        if (tid < 512) {
            int tt = tid >> 6, dd = tid & 63;
            float s = 0.f;
#pragma unroll
            for (int hh = 0; hh < 16; hh++) s += p_s[(hh * 8 + tt) * 64 + dd];
            outb[(size_t)(g8 * 8 + tt) * TD + dd] = s;
        }
        __syncthreads();
    }
}

// ---------------- launch ----------------------------------------------------
extern "C" void kernel_launch(void* const* d_in, const int* in_sizes, int n_in,
                              void* d_out, int out_size)
{
    const float* x = (const float*)d_in[0];   // inputs    [4,4096,1024]
    const float* w = (const float*)d_in[1];   // kv_kernel [1024,16,64,2]
    const float* q = (const float*)d_in[2];   // q_kernel  [16,64]
    float* out = (float*)d_out;               // [4,4096,64] f32

    cvt_kernel<<<(NX4 + NW4) / 256, 256>>>((const float4*)x, (const float4*)w);

    cudaFuncSetAttribute(gemm_kernel,
                         cudaFuncAttributeMaxDynamicSharedMemorySize, 100864);
    gemm_kernel<<<dim3(16, 128), 256, 100864>>>(q);

    partial_kernel<<<dim3(16, 64), 256>>>();
    scanagg_kernel<<<64, TD>>>();
    final_kernel<<<dim3(NC, TB), 1024>>>(out);
}